// round 16
// baseline (speedup 1.0000x reference)
#include <cuda_runtime.h>
#include <cuda_bf16.h>
#include <math.h>

#define NN 10000      // nodes
#define TT 12         // seq len
#define FIN 16        // in channels
#define HH 64         // hidden
#define NE 160000     // edges
#define MB 80         // nodes per block (10000 = 125 * 80)
#define GRID_REC 125
#define NTH 768       // 24 warps: 2 K-halves x 12 N-role warps

typedef unsigned int u32;
typedef unsigned long long u64;

// ---------------- scratch (device globals; no allocation allowed) ----------
__device__ float g_deg[NN];                  // deg, then dis = rsqrt(deg)
__device__ u32  g_aggh[NN * TT * 8];         // packed bf16 agg: 16 per (n,t) row
__device__ u32  g_xbf [NN * TT * 8];         // packed bf16 x, t-major (t*NN+n)

// ---------------- helpers ----------------------------------------------------
__device__ __forceinline__ float tanh_fast(float x) {
    float y; asm("tanh.approx.f32 %0, %1;" : "=f"(y) : "f"(x)); return y;
}
__device__ __forceinline__ float sigmoid_fast(float x) {
    return fmaf(0.5f, tanh_fast(0.5f * x), 0.5f);
}
__device__ __forceinline__ u32 pack2f(float a, float b) {
    return (u32)__bfloat16_as_ushort(__float2bfloat16(a))
         | ((u32)__bfloat16_as_ushort(__float2bfloat16(b)) << 16);
}
__device__ __forceinline__ void unp2(u32 p, float& a, float& b) {
    a = __bfloat162float(__ushort_as_bfloat16((unsigned short)(p & 0xffffu)));
    b = __bfloat162float(__ushort_as_bfloat16((unsigned short)(p >> 16)));
}
__device__ __forceinline__ u32 mulbf2(u32 a, u32 b) {
    u32 r; asm("mul.bf16x2 %0, %1, %2;" : "=r"(r) : "r"(a), "r"(b)); return r;
}
__device__ __forceinline__ void mma16816(float* c, const u32* a, u32 b0, u32 b1) {
    asm volatile(
        "mma.sync.aligned.m16n8k16.row.col.f32.bf16.bf16.f32 "
        "{%0,%1,%2,%3}, {%4,%5,%6,%7}, {%8,%9}, {%0,%1,%2,%3};"
        : "+f"(c[0]), "+f"(c[1]), "+f"(c[2]), "+f"(c[3])
        : "r"(a[0]), "r"(a[1]), "r"(a[2]), "r"(a[3]), "r"(b0), "r"(b1));
}
__device__ __forceinline__ void ldm4(u32* r, u32 saddr) {
    asm volatile("ldmatrix.sync.aligned.m8n8.x4.shared.b16 {%0,%1,%2,%3}, [%4];"
                 : "=r"(r[0]), "=r"(r[1]), "=r"(r[2]), "=r"(r[3]) : "r"(saddr));
}

// ---------------- degree / prep --------------------------------------------
__global__ void k_deg_init() {
    int i = blockIdx.x * blockDim.x + threadIdx.x;
    if (i < NN) g_deg[i] = 1.0f;
}
__global__ void k_deg_edge(const int* __restrict__ ei) {
    int e = blockIdx.x * blockDim.x + threadIdx.x;
    if (e < NE) atomicAdd(&g_deg[ei[NE + e]], 1.0f);
}
__global__ void k_dis() {   // deg -> dis in place
    int i = blockIdx.x * blockDim.x + threadIdx.x;
    if (i < NN) g_deg[i] = rsqrtf(g_deg[i]);
}
// agg init + x bf16 pre-convert (g_deg holds dis here)
__global__ void k_agg_init(const float* __restrict__ x) {
    int idx = blockIdx.x * blockDim.x + threadIdx.x;   // (t,n,q) t-major
    if (idx >= NN * TT * 2) return;
    int q = idx & 1;
    int tn = idx >> 1;
    int n = tn % NN, t = tn / NN;
    const float4* xr = reinterpret_cast<const float4*>(&x[((size_t)tn * 16) + q * 8]);
    float4 v0 = xr[0], v1 = xr[1];
    uint4 raw;
    raw.x = pack2f(v0.x, v0.y);
    raw.y = pack2f(v0.z, v0.w);
    raw.z = pack2f(v1.x, v1.y);
    raw.w = pack2f(v1.z, v1.w);
    reinterpret_cast<uint4*>(g_xbf)[idx] = raw;
    float di = g_deg[n];
    float c = di * di;
    uint4 o;
    o.x = pack2f(v0.x * c, v0.y * c);
    o.y = pack2f(v0.z * c, v0.w * c);
    o.z = pack2f(v1.x * c, v1.y * c);
    o.w = pack2f(v1.z * c, v1.w * c);
    reinterpret_cast<uint4*>(g_aggh)[(size_t)n * (TT * 2) + t * 2 + q] = o;
}
// edge scatter: thread = (edge, chunk); warp-shuffled edge metadata.
__global__ void k_edge_agg(const int* __restrict__ ei) {
    int gt = blockIdx.x * blockDim.x + threadIdx.x;
    int lane = threadIdx.x & 31;
    int e = gt / 24, ch = gt - e * 24;
    int eBase = (gt - lane) / 24;            // first edge this warp touches
    // lanes 0-2 load metadata for edges eBase..eBase+2
    int sL = 0; u32 ccL = 0;
    if (lane < 3) {
        int eL = eBase + lane;
        if (eL < NE) {
            int s = ei[eL];
            int d = ei[NE + eL];
            float c = g_deg[s] * g_deg[d];   // dis*dis
            sL = s;
            ccL = pack2f(c, c) & 0xffffffffu;
            // stash d in upper bits? need both s,d: use two shuffles
            (void)d;
        }
    }
    int dL = 0;
    if (lane < 3) {
        int eL = eBase + lane;
        if (eL < NE) dL = ei[NE + eL];
    }
    int rel = e - eBase;                     // 0..2
    int s = __shfl_sync(0xffffffffu, sL, rel);
    int d = __shfl_sync(0xffffffffu, dL, rel);
    u32 cc = __shfl_sync(0xffffffffu, ccL, rel);
    int t = ch >> 1, qh = ch & 1;
    uint4 v = reinterpret_cast<const uint4*>(g_xbf)[((size_t)t * NN + s) * 2 + qh];
    u32 p0 = mulbf2(v.x, cc);
    u32 p1 = mulbf2(v.y, cc);
    u32 p2 = mulbf2(v.z, cc);
    u32 p3 = mulbf2(v.w, cc);
    u32* dst = g_aggh + (size_t)d * (TT * 8) + ch * 4;
    asm volatile("red.global.add.noftz.v4.bf16x2 [%0], {%1, %2, %3, %4};"
                 :: "l"(dst), "r"(p0), "r"(p1), "r"(p2), "r"(p3) : "memory");
}

// ---------------- fused 2-layer HMMA GRU + attention kernel ------------------
// 24 warps = 2 K-halves x {8 rz + 2 xn + 2 hn}. Single-term bf16 weights.
// Per t: MMA L0 -> gates L0 (h1 -> A0.H, A1.X) -> MMA L1 -> gates L1
// (h2 -> A1.H, online-softmax attention). fp32 h carry in registers.
#define OFF_A0   0               // bf16 A tile L0 [80 x 256B]: x | h1prev
#define OFF_A1   20480           // bf16 A tile L1 [80 x 256B]: h1 | h2prev
#define OFF_GRZ0 40960           // fp32 [80][128] swizzled, K-half 0
#define OFF_GRZ1 81920
#define OFF_GX0  122880          // fp32 [80][64]
#define OFF_GX1  143360
#define OFF_GH0  163840
#define OFF_GH1  184320
#define OFF_CTX  204800          // fp32 [80][64]
#define OFF_MS   225280
#define OFF_ZS   225600
#define OFF_B0   225920          // 256 floats
#define OFF_B1   226944
#define OFF_GW   227968          // 1024 floats
#define OFF_GB   232064          // 64 floats
#define SMEM_F   232320

// single-term m-tile: acc += a * b
template<int KKS, int NTS>
__device__ __forceinline__ void mma_m_tile(
    u32 a_base, int kbyte, int swrow, int kk0,
    const u32* bh, float* acc)
{
#pragma unroll
    for (int q = 0; q < NTS * 4; q++) acc[q] = 0.f;
#pragma unroll
    for (int kk = 0; kk < KKS; kk++) {
        u32 off = (u32)((((kk + kk0) * 32) + kbyte) ^ swrow);
        u32 ah[4];
        ldm4(ah, a_base + off);
#pragma unroll
        for (int nt = 0; nt < NTS; nt++) {
            int f = kk * NTS + nt;
            mma16816(acc + nt * 4, ah, bh[2 * f], bh[2 * f + 1]);
        }
    }
}

__global__ __launch_bounds__(NTH, 1) void k_recf(
    const float* __restrict__ wih0, const float* __restrict__ whh0,
    const float* __restrict__ bih0, const float* __restrict__ bhh0,
    const float* __restrict__ wih1, const float* __restrict__ whh1,
    const float* __restrict__ bih1, const float* __restrict__ bhh1,
    const float* __restrict__ gwp, const float* __restrict__ gbp,
    const float* __restrict__ awp, const float* __restrict__ abp,
    const float* __restrict__ fwp, const float* __restrict__ fbp,
    const float* __restrict__ x,   float* __restrict__ outv)
{
    extern __shared__ __align__(16) char sm[];
    char* A0   = sm + OFF_A0;
    char* A1   = sm + OFF_A1;
    char* GRZ0 = sm + OFF_GRZ0;
    char* GRZ1 = sm + OFF_GRZ1;
    char* GX0  = sm + OFF_GX0;
    char* GX1  = sm + OFF_GX1;
    char* GH0  = sm + OFF_GH0;
    char* GH1  = sm + OFF_GH1;
    float* ctx = (float*)(sm + OFF_CTX);
    float* mS  = (float*)(sm + OFF_MS);
    float* ZS  = (float*)(sm + OFF_ZS);
    float* bias0 = (float*)(sm + OFF_B0);
    float* bias1 = (float*)(sm + OFF_B1);
    float* gwS = (float*)(sm + OFF_GW);
    float* gbS = (float*)(sm + OFF_GB);

    int tid = threadIdx.x, wid = tid >> 5, lid = tid & 31;
    int g = lid >> 2, tg = lid & 3;
    int node0 = blockIdx.x * MB;
    int wl = wid % 12;          // N-role warp index
    int half = wid / 12;        // K-half

    if (tid < 128) { bias0[tid] = bih0[tid] + bhh0[tid]; bias1[tid] = bih1[tid] + bhh1[tid]; }
    else if (tid < 192) { bias0[tid] = bih0[tid]; bias1[tid] = bih1[tid]; }
    else if (tid < 256) { bias0[tid] = bhh0[tid - 64]; bias1[tid] = bhh1[tid - 64]; }
    for (int i = tid; i < FIN * HH; i += NTH) gwS[i] = gwp[i];
    if (tid >= 256 && tid < 320) gbS[tid - 256] = gbp[tid - 256];
    for (int i = tid; i < MB * 64; i += NTH) ctx[i] = 0.0f;
    if (tid >= 320 && tid < 320 + MB) { mS[tid - 320] = -3.0e38f; ZS[tid - 320] = 0.0f; }
    {
        uint4 z = make_uint4(0, 0, 0, 0);
        for (int i = tid; i < 2560; i += NTH) ((uint4*)A0)[i] = z;   // A0 + A1
    }

    bool is_rz = wl < 8;
    int role = is_rz ? 0 : (wl < 10 ? 1 : 2);
    int kk0 = is_rz ? half * 4 : half * 2;

    // persistent B fragments for BOTH layers: bf16 weights, 8 slots x 2 regs
    u32 bh0[16], bh1[16];
#pragma unroll
    for (int f = 0; f < 8; f++) {
        int kk = is_rz ? (f >> 1) : (f >> 2);
        int nt = is_rz ? (f & 1)  : (f & 3);
        int nrow;
        if (role == 0)      nrow = wl * 16 + nt * 8 + g;
        else if (role == 1) nrow = 128 + (wl - 8) * 32 + nt * 8 + g;
        else                nrow = 128 + (wl - 10) * 32 + nt * 8 + g;
#pragma unroll
        for (int r = 0; r < 2; r++) {
            int k = (kk + kk0) * 16 + tg * 2 + r * 8;
            float w0, w1, v0, v1;
            if (role == 0) {
                if (k < 64) {
                    w0 = wih0[nrow * 64 + k];      w1 = wih0[nrow * 64 + k + 1];
                    v0 = wih1[nrow * 64 + k];      v1 = wih1[nrow * 64 + k + 1];
                } else {
                    w0 = whh0[nrow * 64 + k - 64]; w1 = whh0[nrow * 64 + k - 63];
                    v0 = whh1[nrow * 64 + k - 64]; v1 = whh1[nrow * 64 + k - 63];
                }
            } else if (role == 1) {
                w0 = wih0[nrow * 64 + k]; w1 = wih0[nrow * 64 + k + 1];
                v0 = wih1[nrow * 64 + k]; v1 = wih1[nrow * 64 + k + 1];
            } else {
                w0 = whh0[nrow * 64 + k]; w1 = whh0[nrow * 64 + k + 1];
                v0 = whh1[nrow * 64 + k]; v1 = whh1[nrow * 64 + k + 1];
            }
            bh0[2 * f + r] = pack2f(w0, w1);
            bh1[2 * f + r] = pack2f(v0, v1);
        }
    }

    int aoff = (role == 2) ? 128 : 0;
    int quad = lid >> 3;
    int rloc = (lid & 7) + ((quad & 1) << 3);
    int kbyte = (quad >> 1) << 4;
    int swrow = (rloc & 7) << 4;
    u32 A0_s = (u32)__cvta_generic_to_shared(A0);
    u32 A1_s = (u32)__cvta_generic_to_shared(A1);

    float aw0 = awp[2 * lid], aw1 = awp[2 * lid + 1];
    float fw0 = fwp[2 * lid], fw1 = fwp[2 * lid + 1];
    float ab = abp[0];

    // fp32 h carry in registers: up to 4 (row,jp) pairs per thread, 2 vals each
    float hc0[8], hc1[8];
#pragma unroll
    for (int i = 0; i < 8; i++) { hc0[i] = 0.f; hc1[i] = 0.f; }

    // stage x(tt) -> A0.X (inline GCN from g_aggh)
    auto stage_x = [&](int tt) {
        for (int i = tid; i < MB * 16; i += NTH) {
            int m = i >> 4, j = i & 15;
            const uint4* ar = reinterpret_cast<const uint4*>(
                g_aggh + (((size_t)(node0 + m)) * TT + tt) * 8);
            uint4 qa = ar[0], qb = ar[1];
            float a[16];
            unp2(qa.x, a[0], a[1]);  unp2(qa.y, a[2], a[3]);
            unp2(qa.z, a[4], a[5]);  unp2(qa.w, a[6], a[7]);
            unp2(qb.x, a[8], a[9]);  unp2(qb.y, a[10], a[11]);
            unp2(qb.z, a[12], a[13]); unp2(qb.w, a[14], a[15]);
            float s0 = gbS[4 * j], s1 = gbS[4 * j + 1], s2 = gbS[4 * j + 2], s3 = gbS[4 * j + 3];
#pragma unroll
            for (int f = 0; f < 16; f++) {
                const float4 wv = reinterpret_cast<const float4*>(gwS)[f * 16 + j];
                s0 = fmaf(a[f], wv.x, s0);
                s1 = fmaf(a[f], wv.y, s1);
                s2 = fmaf(a[f], wv.z, s2);
                s3 = fmaf(a[f], wv.w, s3);
            }
            s0 = fmaxf(s0, 0.f); s1 = fmaxf(s1, 0.f);
            s2 = fmaxf(s2, 0.f); s3 = fmaxf(s3, 0.f);
            uint2 phv;
            phv.x = pack2f(s0, s1);
            phv.y = pack2f(s2, s3);
            int byt = m * 256 + ((8 * j) ^ ((m & 7) << 4));
            *(uint2*)(A0 + byt) = phv;
        }
    };

    // MMA phase: 5 m-tiles into G buffers
    auto mma_phase = [&](u32 As, const u32* bh) {
        for (int m = 0; m < 5; m++) {
            float acc[16];
            u32 rowb = (u32)((m * 16 + rloc) * 256 + aoff);
            if (is_rz) mma_m_tile<4, 2>(As + rowb, kbyte, swrow, kk0, bh, acc);
            else       mma_m_tile<2, 4>(As + rowb, kbyte, swrow, kk0, bh, acc);
            int row0 = m * 16 + g;
            int swG = g << 5;
            if (role == 0) {
                char* Gp = half ? GRZ1 : GRZ0;
#pragma unroll
                for (int nt = 0; nt < 2; nt++) {
                    int b = (4 * (wl * 16 + nt * 8 + tg * 2)) ^ swG;
                    *(float2*)(Gp + row0 * 512 + b)       = make_float2(acc[nt * 4 + 0], acc[nt * 4 + 1]);
                    *(float2*)(Gp + (row0 + 8) * 512 + b) = make_float2(acc[nt * 4 + 2], acc[nt * 4 + 3]);
                }
            } else {
                char* Gp = (role == 1) ? (half ? GX1 : GX0) : (half ? GH1 : GH0);
                int wb = (role == 1) ? (wl - 8) : (wl - 10);
#pragma unroll
                for (int nt = 0; nt < 4; nt++) {
                    int b = (4 * (wb * 32 + nt * 8 + tg * 2)) ^ swG;
                    *(float2*)(Gp + row0 * 256 + b)       = make_float2(acc[nt * 4 + 0], acc[nt * 4 + 1]);
                    *(float2*)(Gp + (row0 + 8) * 256 + b) = make_float2(acc[nt * 4 + 2], acc[nt * 4 + 3]);
                }
            }
        }
    };

    stage_x(0);
    __syncthreads();

    for (int t = 0; t < TT; t++) {
        // ======== layer 0 ========
        mma_phase(A0_s, bh0);
        __syncthreads();
#pragma unroll
        for (int it = 0; it < 4; it++) {
            int p = tid + it * NTH;
            if (p < MB * 32) {
                int row = p >> 5, jp = p & 31;
                int o = (8 * jp) ^ ((row & 7) << 5);
                float2 rva = *(float2*)(GRZ0 + row * 512 + o);
                float2 rvb = *(float2*)(GRZ1 + row * 512 + o);
                float2 zva = *(float2*)(GRZ0 + row * 512 + 256 + o);
                float2 zvb = *(float2*)(GRZ1 + row * 512 + 256 + o);
                float2 xva = *(float2*)(GX0 + row * 256 + o);
                float2 xvb = *(float2*)(GX1 + row * 256 + o);
                float2 hva = *(float2*)(GH0 + row * 256 + o);
                float2 hvb = *(float2*)(GH1 + row * 256 + o);
                int i0 = 2 * jp;
                float r0 = sigmoid_fast(rva.x + rvb.x + bias0[i0]);
                float r1 = sigmoid_fast(rva.y + rvb.y + bias0[i0 + 1]);
                float z0 = sigmoid_fast(zva.x + zvb.x + bias0[64 + i0]);
                float z1 = sigmoid_fast(zva.y + zvb.y + bias0[64 + i0 + 1]);
                float n0 = tanh_fast(xva.x + xvb.x + bias0[128 + i0]     + r0 * (hva.x + hvb.x + bias0[192 + i0]));
                float n1 = tanh_fast(xva.y + xvb.y + bias0[128 + i0 + 1] + r1 * (hva.y + hvb.y + bias0[192 + i0 + 1]));
                float o0 = fmaf(z0, hc0[it * 2] - n0, n0);
                float o1 = fmaf(z1, hc0[it * 2 + 1] - n1, n1);
                hc0[it * 2] = o0; hc0[it * 2 + 1] = o1;
                u32 hip = pack2f(o0, o1);
                int swz = (4 * jp) ^ ((row & 7) << 4);
                *(u32*)(A0 + row * 256 + 128 + swz) = hip;   // L0 h state
                *(u32*)(A1 + row * 256 + swz) = hip;         // L1 input
            }
        }
        __syncthreads();
        // ======== layer 1 ========
        mma_phase(A1_s, bh1);
        __syncthreads();
#pragma unroll
        for (int it = 0; it < 4; it++) {
            int p = tid + it * NTH;
            if (p < MB * 32) {
                int row = p >> 5, jp = p & 31;
                int o = (8 * jp) ^ ((row & 7) << 5);
                float2 rva = *(float2*)(GRZ0 + row * 512 + o);
                float2 rvb = *(float2*)(GRZ1 + row * 512 + o);
                float2 zva = *(float2*)(GRZ0 + row * 512 + 256 + o);
                float2 zvb = *(float2*)(GRZ1 + row * 512 + 256 + o);
                float2 xva = *(float2*)(GX0 + row * 256 + o);
                float2 xvb = *(float2*)(GX1 + row * 256 + o);
                float2 hva = *(float2*)(GH0 + row * 256 + o);
                float2 hvb = *(float2*)(GH1 + row * 256 + o);
                int i0 = 2 * jp;
                float r0 = sigmoid_fast(rva.x + rvb.x + bias1[i0]);
                float r1 = sigmoid_fast(rva.y + rvb.y + bias1[i0 + 1]);
                float z0 = sigmoid_fast(zva.x + zvb.x + bias1[64 + i0]);
                float z1 = sigmoid_fast(zva.y + zvb.y + bias1[64 + i0 + 1]);
                float n0 = tanh_fast(xva.x + xvb.x + bias1[128 + i0]     + r0 * (hva.x + hvb.x + bias1[192 + i0]));
                float n1 = tanh_fast(xva.y + xvb.y + bias1[128 + i0 + 1] + r1 * (hva.y + hvb.y + bias1[192 + i0 + 1]));
                float o0 = fmaf(z0, hc1[it * 2] - n0, n0);
                float o1 = fmaf(z1, hc1[it * 2 + 1] - n1, n1);
                hc1[it * 2] = o0; hc1[it * 2 + 1] = o1;
                u32 hip = pack2f(o0, o1);
                int swz = (4 * jp) ^ ((row & 7) << 4);
                *(u32*)(A1 + row * 256 + 128 + swz) = hip;   // L1 h state
                // online softmax attention over t
                float sc = o0 * aw0 + o1 * aw1;
#pragma unroll
                for (int of = 16; of > 0; of >>= 1) sc += __shfl_xor_sync(0xffffffffu, sc, of);
                sc += ab;
                float m_old = mS[row];
                float mn = fmaxf(m_old, sc);
                float ea = __expf(m_old - mn);
                float eb = __expf(sc - mn);
                ctx[row * 64 + i0]     = ctx[row * 64 + i0]     * ea + eb * o0;
                ctx[row * 64 + i0 + 1] = ctx[row * 64 + i0 + 1] * ea + eb * o1;
                if (jp == 0) { mS[row] = mn; ZS[row] = ZS[row] * ea + eb; }
            }
        }
        if (t + 1 < TT) stage_x(t + 1);   // overlap next x staging
        __syncthreads();
    }

    // epilogue: fc + residual -> output
    for (int row = wid; row < MB; row += 24) {
        float v = ctx[row * 64 + 2 * lid] * fw0 + ctx[row * 64 + 2 * lid + 1] * fw1;
#pragma unroll
        for (int of = 16; of > 0; of >>= 1) v += __shfl_xor_sync(0xffffffffu, v, of);
        if (lid == 0) {
            int node = node0 + row;
            float last = x[((size_t)(TT - 1) * NN + node) * FIN];
            outv[node] = last + v / ZS[row] + fbp[0];
        }
    }
}

// ---------------- launch ----------------------------------------------------
extern "C" void kernel_launch(void* const* d_in, const int* in_sizes, int n_in,
                              void* d_out, int out_size) {
    const float* x      = (const float*)d_in[0];
    const int*   ei     = (const int*)  d_in[1];
    const float* gcn_w  = (const float*)d_in[2];
    const float* gcn_b  = (const float*)d_in[3];
    const float* w_ih0  = (const float*)d_in[4];
    const float* w_hh0  = (const float*)d_in[5];
    const float* b_ih0  = (const float*)d_in[6];
    const float* b_hh0  = (const float*)d_in[7];
    const float* w_ih1  = (const float*)d_in[8];
    const float* w_hh1  = (const float*)d_in[9];
    const float* b_ih1  = (const float*)d_in[10];
    const float* b_hh1  = (const float*)d_in[11];
    const float* attn_w = (const float*)d_in[12];
    const float* attn_b = (const float*)d_in[13];
    const float* fc_w   = (const float*)d_in[14];
    const float* fc_b   = (const float*)d_in[15];
    float* out = (float*)d_out;

    cudaFuncSetAttribute(k_recf, cudaFuncAttributeMaxDynamicSharedMemorySize, SMEM_F);

    k_deg_init<<<(NN + 255) / 256, 256>>>();
    k_deg_edge<<<(NE + 255) / 256, 256>>>(ei);
    k_dis<<<(NN + 255) / 256, 256>>>();
    k_agg_init<<<(NN * TT * 2 + 255) / 256, 256>>>(x);
    k_edge_agg<<<(NE * 24 + 255) / 256, 256>>>(ei);

    k_recf<<<GRID_REC, NTH, SMEM_F>>>(w_ih0, w_hh0, b_ih0, b_hh0,
                                      w_ih1, w_hh1, b_ih1, b_hh1,
                                      gcn_w, gcn_b, attn_w, attn_b, fc_w, fc_b,
                                      x, out);
}

// round 17
// speedup vs baseline: 1.0695x; 1.0695x over previous
#include <cuda_runtime.h>
#include <cuda_bf16.h>
#include <math.h>

#define NN 10000      // nodes
#define TT 12         // seq len
#define FIN 16        // in channels
#define HH 64         // hidden
#define NE 160000     // edges
#define MB 80         // nodes per block (10000 = 125 * 80)
#define GRID_REC 125
#define NTH 768       // 24 warps: 2 K-halves x 12 N-role warps

typedef unsigned int u32;
typedef unsigned long long u64;

// ---------------- scratch (device globals; no allocation allowed) ----------
__device__ float g_deg[NN];                  // deg, then dis = rsqrt(deg)
__device__ u32  g_aggh[NN * TT * 8];         // packed bf16 agg: 16 per (n,t) row
__device__ u32  g_xbf [NN * TT * 8];         // packed bf16 x, t-major (t*NN+n)
__device__ u32  g_hap[NN * TT * (HH / 2)];   // packed bf16 hi-pairs (h1)

// ---------------- helpers ----------------------------------------------------
__device__ __forceinline__ float tanh_fast(float x) {
    float y; asm("tanh.approx.f32 %0, %1;" : "=f"(y) : "f"(x)); return y;
}
__device__ __forceinline__ float sigmoid_fast(float x) {
    return fmaf(0.5f, tanh_fast(0.5f * x), 0.5f);
}
__device__ __forceinline__ u32 pack2f(float a, float b) {
    return (u32)__bfloat16_as_ushort(__float2bfloat16(a))
         | ((u32)__bfloat16_as_ushort(__float2bfloat16(b)) << 16);
}
__device__ __forceinline__ void unp2(u32 p, float& a, float& b) {
    a = __bfloat162float(__ushort_as_bfloat16((unsigned short)(p & 0xffffu)));
    b = __bfloat162float(__ushort_as_bfloat16((unsigned short)(p >> 16)));
}
__device__ __forceinline__ u32 mulbf2(u32 a, u32 b) {
    u32 r; asm("mul.bf16x2 %0, %1, %2;" : "=r"(r) : "r"(a), "r"(b)); return r;
}
__device__ __forceinline__ void mma16816(float* c, const u32* a, u32 b0, u32 b1) {
    asm volatile(
        "mma.sync.aligned.m16n8k16.row.col.f32.bf16.bf16.f32 "
        "{%0,%1,%2,%3}, {%4,%5,%6,%7}, {%8,%9}, {%0,%1,%2,%3};"
        : "+f"(c[0]), "+f"(c[1]), "+f"(c[2]), "+f"(c[3])
        : "r"(a[0]), "r"(a[1]), "r"(a[2]), "r"(a[3]), "r"(b0), "r"(b1));
}
__device__ __forceinline__ void ldm4(u32* r, u32 saddr) {
    asm volatile("ldmatrix.sync.aligned.m8n8.x4.shared.b16 {%0,%1,%2,%3}, [%4];"
                 : "=r"(r[0]), "=r"(r[1]), "=r"(r[2]), "=r"(r[3]) : "r"(saddr));
}

// ---------------- degree / prep --------------------------------------------
__global__ void k_deg_init() {
    int i = blockIdx.x * blockDim.x + threadIdx.x;
    if (i < NN) g_deg[i] = 1.0f;
}
__global__ void k_deg_edge(const int* __restrict__ ei) {
    int e = blockIdx.x * blockDim.x + threadIdx.x;
    if (e < NE) atomicAdd(&g_deg[ei[NE + e]], 1.0f);
}
__global__ void k_dis() {   // deg -> dis in place
    int i = blockIdx.x * blockDim.x + threadIdx.x;
    if (i < NN) g_deg[i] = rsqrtf(g_deg[i]);
}
// agg init + x bf16 pre-convert (g_deg holds dis)
__global__ void k_agg_init(const float* __restrict__ x) {
    int idx = blockIdx.x * blockDim.x + threadIdx.x;   // (t,n,q) t-major
    if (idx >= NN * TT * 2) return;
    int q = idx & 1;
    int tn = idx >> 1;
    int n = tn % NN, t = tn / NN;
    const float4* xr = reinterpret_cast<const float4*>(&x[((size_t)tn * 16) + q * 8]);
    float4 v0 = xr[0], v1 = xr[1];
    // raw bf16 copy (unscaled) for edge kernel
    uint4 raw;
    raw.x = pack2f(v0.x, v0.y);
    raw.y = pack2f(v0.z, v0.w);
    raw.z = pack2f(v1.x, v1.y);
    raw.w = pack2f(v1.z, v1.w);
    reinterpret_cast<uint4*>(g_xbf)[idx] = raw;
    // self-loop init term, scaled by 1/deg = dis*dis
    float di = g_deg[n];
    float c = di * di;
    uint4 o;
    o.x = pack2f(v0.x * c, v0.y * c);
    o.y = pack2f(v0.z * c, v0.w * c);
    o.z = pack2f(v1.x * c, v1.y * c);
    o.w = pack2f(v1.z * c, v1.w * c);
    reinterpret_cast<uint4*>(g_aggh)[(size_t)n * (TT * 2) + t * 2 + q] = o;
}
// edge scatter: thread = (edge, chunk), 24 chunks/edge, full utilization.
__global__ void k_edge_agg(const int* __restrict__ ei) {
    int gt = blockIdx.x * blockDim.x + threadIdx.x;
    int e = gt / 24, ch = gt - e * 24;
    if (e >= NE) return;
    int s = ei[e];
    int d = ei[NE + e];
    float c = g_deg[s] * g_deg[d];           // dis * dis (precomputed)
    u32 cc = pack2f(c, c);
    int t = ch >> 1, qh = ch & 1;
    uint4 v = reinterpret_cast<const uint4*>(g_xbf)[((size_t)t * NN + s) * 2 + qh];
    u32 p0 = mulbf2(v.x, cc);
    u32 p1 = mulbf2(v.y, cc);
    u32 p2 = mulbf2(v.z, cc);
    u32 p3 = mulbf2(v.w, cc);
    u32* dst = g_aggh + (size_t)d * (TT * 8) + ch * 4;
    asm volatile("red.global.add.noftz.v4.bf16x2 [%0], {%1, %2, %3, %4};"
                 :: "l"(dst), "r"(p0), "r"(p1), "r"(p2), "r"(p3) : "memory");
}

// ---------------- fused HMMA GRU layers (R15 proven structure) ---------------
// 24 warps = 2 K-halves x {8 rz + 2 xn + 2 hn}. Single-term bf16 weights.
#define OFF_AHI  0               // bf16 A tile [80 x 256B]: X half | H half
#define OFF_GRZ0 20480           // fp32 [80][128] swizzled, K-half 0
#define OFF_GRZ1 61440           // K-half 1
#define OFF_GX0  102400          // fp32 [80][64]
#define OFF_GX1  122880
#define OFF_GH0  143360
#define OFF_GH1  163840
#define OFF_HS   184320          // fp32 h state [80][64]
#define OFF_B    204800          // biases: 256 floats
#define OFF_EXT  205824
#define SMEM_L0 (OFF_EXT + 4096 + 256)
#define SMEM_L1 (OFF_EXT + 20480 + 640 + 256 + 256 + 16)

// single-term m-tile: acc += a * b
template<int KKS, int NTS>
__device__ __forceinline__ void mma_m_tile(
    u32 a_base, int kbyte, int swrow, int kk0,
    const u32* bh, float* acc)
{
#pragma unroll
    for (int q = 0; q < NTS * 4; q++) acc[q] = 0.f;
#pragma unroll
    for (int kk = 0; kk < KKS; kk++) {
        u32 off = (u32)((((kk + kk0) * 32) + kbyte) ^ swrow);
        u32 ah[4];
        ldm4(ah, a_base + off);
#pragma unroll
        for (int nt = 0; nt < NTS; nt++) {
            int f = kk * NTS + nt;
            mma16816(acc + nt * 4, ah, bh[2 * f], bh[2 * f + 1]);
        }
    }
}

template<int L>
__global__ __launch_bounds__(NTH, 1) void k_rec(
    const float* __restrict__ wih, const float* __restrict__ whh,
    const float* __restrict__ bih, const float* __restrict__ bhh,
    const float* __restrict__ gwp, const float* __restrict__ gbp,
    const float* __restrict__ awp, const float* __restrict__ abp,
    const float* __restrict__ fwp, const float* __restrict__ fbp,
    const float* __restrict__ x,   float* __restrict__ outv)
{
    extern __shared__ __align__(16) char sm[];
    char* AHI  = sm + OFF_AHI;
    char* GRZ0 = sm + OFF_GRZ0;
    char* GRZ1 = sm + OFF_GRZ1;
    char* GX0  = sm + OFF_GX0;
    char* GX1  = sm + OFF_GX1;
    char* GH0  = sm + OFF_GH0;
    char* GH1  = sm + OFF_GH1;
    float* hS   = (float*)(sm + OFF_HS);
    float* bias = (float*)(sm + OFF_B);
    float* gwS = (float*)(sm + OFF_EXT);
    float* gbS = (float*)(sm + OFF_EXT + 4096);
    float* ctx = (float*)(sm + OFF_EXT);
    float* mS  = (float*)(sm + OFF_EXT + 20480);
    float* ZS  = (float*)(sm + OFF_EXT + 20480 + 320);
    float* awS = (float*)(sm + OFF_EXT + 21120);
    float* fwS = (float*)(sm + OFF_EXT + 21376);
    float* scS = (float*)(sm + OFF_EXT + 21632);

    int tid = threadIdx.x, wid = tid >> 5, lid = tid & 31;
    int g = lid >> 2, tg = lid & 3;
    int node0 = blockIdx.x * MB;
    int wl = wid % 12;          // N-role warp index
    int half = wid / 12;        // K-half

    if (tid < 128) bias[tid] = bih[tid] + bhh[tid];
    else if (tid < 192) bias[tid] = bih[tid];
    else if (tid < 256) bias[tid] = bhh[tid - 64];

    if (L == 0) {
        for (int i = tid; i < FIN * HH; i += NTH) gwS[i] = gwp[i];
        if (tid >= 256 && tid < 320) gbS[tid - 256] = gbp[tid - 256];
    } else {
        for (int i = tid; i < MB * 64; i += NTH) ctx[i] = 0.0f;
        if (tid >= 256 && tid < 256 + MB) { mS[tid - 256] = -3.0e38f; ZS[tid - 256] = 0.0f; }
        if (tid >= 384 && tid < 448) { awS[tid - 384] = awp[tid - 384]; fwS[tid - 384] = fwp[tid - 384]; }
        if (tid == 448) scS[0] = abp[0];
    }

    {
        uint4 z = make_uint4(0, 0, 0, 0);
        for (int i = tid; i < 1280; i += NTH) ((uint4*)AHI)[i] = z;
        for (int i = tid; i < MB * 64; i += NTH) hS[i] = 0.0f;
    }

    bool is_rz = wl < 8;
    int role = is_rz ? 0 : (wl < 10 ? 1 : 2);
    int kk0 = is_rz ? half * 4 : half * 2;

    // persistent B fragments: bf16 weights, 8 slots x 2 regs
    u32 bh[16];
#pragma unroll
    for (int f = 0; f < 8; f++) {
        int kk = is_rz ? (f >> 1) : (f >> 2);
        int nt = is_rz ? (f & 1)  : (f & 3);
        int nrow;
        if (role == 0)      nrow = wl * 16 + nt * 8 + g;
        else if (role == 1) nrow = 128 + (wl - 8) * 32 + nt * 8 + g;
        else                nrow = 128 + (wl - 10) * 32 + nt * 8 + g;
#pragma unroll
        for (int r = 0; r < 2; r++) {
            int k = (kk + kk0) * 16 + tg * 2 + r * 8;
            float w0, w1;
            if (role == 0) {
                if (k < 64) { w0 = wih[nrow * 64 + k];      w1 = wih[nrow * 64 + k + 1]; }
                else        { w0 = whh[nrow * 64 + k - 64]; w1 = whh[nrow * 64 + k - 63]; }
            } else if (role == 1) {
                w0 = wih[nrow * 64 + k]; w1 = wih[nrow * 64 + k + 1];
            } else {
                w0 = whh[nrow * 64 + k]; w1 = whh[nrow * 64 + k + 1];
            }
            bh[2 * f + r] = pack2f(w0, w1);
        }
    }

    int aoff = (role == 2) ? 128 : 0;
    int quad = lid >> 3;
    int rloc = (lid & 7) + ((quad & 1) << 3);
    int kbyte = (quad >> 1) << 4;
    int swrow = (rloc & 7) << 4;
    u32 AHI_s = (u32)__cvta_generic_to_shared(AHI);

    float aw0 = 0.f, aw1 = 0.f, ab = 0.f;
    __syncthreads();
    if (L == 1) { aw0 = awS[2 * lid]; aw1 = awS[2 * lid + 1]; ab = scS[0]; }

    // stage X(tt) into the X half of the A tile (bf16, swizzled)
    auto stage_x = [&](int tt) {
        if (L == 0) {
            for (int i = tid; i < MB * 16; i += NTH) {
                int m = i >> 4, j = i & 15;
                const uint4* ar = reinterpret_cast<const uint4*>(
                    g_aggh + (((size_t)(node0 + m)) * TT + tt) * 8);
                uint4 qa = ar[0], qb = ar[1];
                float a[16];
                unp2(qa.x, a[0], a[1]);  unp2(qa.y, a[2], a[3]);
                unp2(qa.z, a[4], a[5]);  unp2(qa.w, a[6], a[7]);
                unp2(qb.x, a[8], a[9]);  unp2(qb.y, a[10], a[11]);
                unp2(qb.z, a[12], a[13]); unp2(qb.w, a[14], a[15]);
                float s0 = gbS[4 * j], s1 = gbS[4 * j + 1], s2 = gbS[4 * j + 2], s3 = gbS[4 * j + 3];
#pragma unroll
                for (int f = 0; f < 16; f++) {
                    const float4 wv = reinterpret_cast<const float4*>(gwS)[f * 16 + j];
                    s0 = fmaf(a[f], wv.x, s0);
                    s1 = fmaf(a[f], wv.y, s1);
                    s2 = fmaf(a[f], wv.z, s2);
                    s3 = fmaf(a[f], wv.w, s3);
                }
                s0 = fmaxf(s0, 0.f); s1 = fmaxf(s1, 0.f);
                s2 = fmaxf(s2, 0.f); s3 = fmaxf(s3, 0.f);
                uint2 phv;
                phv.x = pack2f(s0, s1);
                phv.y = pack2f(s2, s3);
                int byt = m * 256 + ((8 * j) ^ ((m & 7) << 4));
                *(uint2*)(AHI + byt) = phv;
            }
        } else {
            const uint2* in8 = reinterpret_cast<const uint2*>(g_hap);
            for (int i = tid; i < MB * 16; i += NTH) {
                int m = i >> 4, j = i & 15;
                uint2 v = in8[((size_t)(node0 + m) * TT + tt) * 16 + j];
                int byt = m * 256 + ((8 * j) ^ ((m & 7) << 4));
                *(uint2*)(AHI + byt) = v;
            }
        }
    };

    stage_x(0);
    __syncthreads();

    for (int t = 0; t < TT; t++) {
        // ---- MMA: 5 m-tiles of 16 rows, each warp its K-half ----
        for (int m = 0; m < 5; m++) {
            float acc[16];
            u32 rowb = (u32)((m * 16 + rloc) * 256 + aoff);
            if (is_rz) mma_m_tile<4, 2>(AHI_s + rowb, kbyte, swrow, kk0, bh, acc);
            else       mma_m_tile<2, 4>(AHI_s + rowb, kbyte, swrow, kk0, bh, acc);

            int row0 = m * 16 + g;
            int swG = g << 5;
            if (role == 0) {
                char* Gp = half ? GRZ1 : GRZ0;
#pragma unroll
                for (int nt = 0; nt < 2; nt++) {
                    int b = (4 * (wl * 16 + nt * 8 + tg * 2)) ^ swG;
                    *(float2*)(Gp + row0 * 512 + b)       = make_float2(acc[nt * 4 + 0], acc[nt * 4 + 1]);
                    *(float2*)(Gp + (row0 + 8) * 512 + b) = make_float2(acc[nt * 4 + 2], acc[nt * 4 + 3]);
                }
            } else {
                char* Gp = (role == 1) ? (half ? GX1 : GX0) : (half ? GH1 : GH0);
                int wb = (role == 1) ? (wl - 8) : (wl - 10);
#pragma unroll
                for (int nt = 0; nt < 4; nt++) {
                    int b = (4 * (wb * 32 + nt * 8 + tg * 2)) ^ swG;
                    *(float2*)(Gp + row0 * 256 + b)       = make_float2(acc[nt * 4 + 0], acc[nt * 4 + 1]);
                    *(float2*)(Gp + (row0 + 8) * 256 + b) = make_float2(acc[nt * 4 + 2], acc[nt * 4 + 3]);
                }
            }
        }
        __syncthreads();

        // ---- gates (+ L1: online-softmax attention); sum K-half partials ----
        for (int p = tid; p < MB * 32; p += NTH) {
            int row = p >> 5, jp = p & 31;
            int sw = (row & 7) << 5;
            int o = (8 * jp) ^ sw;
            float2 rva = *(float2*)(GRZ0 + row * 512 + o);
            float2 rvb = *(float2*)(GRZ1 + row * 512 + o);
            float2 zva = *(float2*)(GRZ0 + row * 512 + 256 + o);
            float2 zvb = *(float2*)(GRZ1 + row * 512 + 256 + o);
            float2 xva = *(float2*)(GX0 + row * 256 + o);
            float2 xvb = *(float2*)(GX1 + row * 256 + o);
            float2 hva = *(float2*)(GH0 + row * 256 + o);
            float2 hvb = *(float2*)(GH1 + row * 256 + o);
            float rx = rva.x + rvb.x, ry = rva.y + rvb.y;
            float zx = zva.x + zvb.x, zy = zva.y + zvb.y;
            float xx = xva.x + xvb.x, xy = xva.y + xvb.y;
            float hx = hva.x + hvb.x, hy = hva.y + hvb.y;
            int i0 = 2 * jp;
            float hp0 = hS[row * 64 + i0], hp1 = hS[row * 64 + i0 + 1];
            float r0 = sigmoid_fast(rx + bias[i0]);
            float r1 = sigmoid_fast(ry + bias[i0 + 1]);
            float z0 = sigmoid_fast(zx + bias[64 + i0]);
            float z1 = sigmoid_fast(zy + bias[64 + i0 + 1]);
            float n0 = tanh_fast(xx + bias[128 + i0]     + r0 * (hx + bias[192 + i0]));
            float n1 = tanh_fast(xy + bias[128 + i0 + 1] + r1 * (hy + bias[192 + i0 + 1]));
            float o0 = fmaf(z0, hp0 - n0, n0);
            float o1 = fmaf(z1, hp1 - n1, n1);
            hS[row * 64 + i0] = o0;
            hS[row * 64 + i0 + 1] = o1;
            u32 hip = pack2f(o0, o1);
            int ba = row * 256 + 128 + ((4 * jp) ^ ((row & 7) << 4));
            *(u32*)(AHI + ba) = hip;
            if (L == 0) {
                g_hap[((size_t)(node0 + row) * TT + t) * 32 + jp] = hip;
            } else {
                float sc = o0 * aw0 + o1 * aw1;
#pragma unroll
                for (int of = 16; of > 0; of >>= 1) sc += __shfl_xor_sync(0xffffffffu, sc, of);
                sc += ab;
                float m_old = mS[row];
                float mn = fmaxf(m_old, sc);
                float ea = __expf(m_old - mn);
                float eb = __expf(sc - mn);
                ctx[row * 64 + i0]     = ctx[row * 64 + i0]     * ea + eb * o0;
                ctx[row * 64 + i0 + 1] = ctx[row * 64 + i0 + 1] * ea + eb * o1;
                if (jp == 0) { mS[row] = mn; ZS[row] = ZS[row] * ea + eb; }
            }
        }
        // ---- overlap: stage next timestep's X while gates warps drain ----
        if (t + 1 < TT) stage_x(t + 1);
        __syncthreads();
    }

    if (L == 1) {
        float fw0 = fwS[2 * lid], fw1 = fwS[2 * lid + 1];
        for (int row = wid; row < MB; row += 24) {
            float v = ctx[row * 64 + 2 * lid] * fw0 + ctx[row * 64 + 2 * lid + 1] * fw1;
#pragma unroll
            for (int of = 16; of > 0; of >>= 1) v += __shfl_xor_sync(0xffffffffu, v, of);
            if (lid == 0) {
                int node = node0 + row;
                float last = x[((size_t)(TT - 1) * NN + node) * FIN];
                outv[node] = last + v / ZS[row] + fbp[0];
            }
        }
    }
}

// ---------------- launch ----------------------------------------------------
extern "C" void kernel_launch(void* const* d_in, const int* in_sizes, int n_in,
                              void* d_out, int out_size) {
    const float* x      = (const float*)d_in[0];
    const int*   ei     = (const int*)  d_in[1];
    const float* gcn_w  = (const float*)d_in[2];
    const float* gcn_b  = (const float*)d_in[3];
    const float* w_ih0  = (const float*)d_in[4];
    const float* w_hh0  = (const float*)d_in[5];
    const float* b_ih0  = (const float*)d_in[6];
    const float* b_hh0  = (const float*)d_in[7];
    const float* w_ih1  = (const float*)d_in[8];
    const float* w_hh1  = (const float*)d_in[9];
    const float* b_ih1  = (const float*)d_in[10];
    const float* b_hh1  = (const float*)d_in[11];
    const float* attn_w = (const float*)d_in[12];
    const float* attn_b = (const float*)d_in[13];
    const float* fc_w   = (const float*)d_in[14];
    const float* fc_b   = (const float*)d_in[15];
    float* out = (float*)d_out;

    cudaFuncSetAttribute(k_rec<0>, cudaFuncAttributeMaxDynamicSharedMemorySize, SMEM_L0);
    cudaFuncSetAttribute(k_rec<1>, cudaFuncAttributeMaxDynamicSharedMemorySize, SMEM_L1);

    k_deg_init<<<(NN + 255) / 256, 256>>>();
    k_deg_edge<<<(NE + 255) / 256, 256>>>(ei);
    k_dis<<<(NN + 255) / 256, 256>>>();
    k_agg_init<<<(NN * TT * 2 + 255) / 256, 256>>>(x);
    k_edge_agg<<<(NE * 24 + 255) / 256, 256>>>(ei);

    k_rec<0><<<GRID_REC, NTH, SMEM_L0>>>(w_ih0, w_hh0, b_ih0, b_hh0,
                                         gcn_w, gcn_b, nullptr, nullptr, nullptr, nullptr,
                                         x, nullptr);
    k_rec<1><<<GRID_REC, NTH, SMEM_L1>>>(w_ih1, w_hh1, b_ih1, b_hh1,
                                         nullptr, nullptr, attn_w, attn_b, fc_w, fc_b,
                                         x, out);
}